// round 2
// baseline (speedup 1.0000x reference)
#include <cuda_runtime.h>
#include <mma.h>
#include <math.h>
#include <stdint.h>
#include <type_traits>

using namespace nvcuda;

#define S_DIM 2048
#define H_DIM 2048
#define NHEAD 16
#define HD    128

// ---------------- scratch (static device globals; no allocation) ----------------
__device__ float g_Q[(size_t)S_DIM * H_DIM];
__device__ float g_K[(size_t)S_DIM * H_DIM];
__device__ float g_V[(size_t)S_DIM * H_DIM];
__device__ float g_attn[(size_t)S_DIM * H_DIM];
__device__ float g_scores[(size_t)NHEAD * S_DIM * S_DIM];  // 256 MB

// round-to-nearest fp32 -> tf32 (result held as fp32 with low 13 mantissa bits zero)
__device__ __forceinline__ float to_tf32(float x) {
    uint32_t u;
    asm("cvt.rna.tf32.f32 %0, %1;" : "=r"(u) : "f"(x));
    return __uint_as_float(u);
}

// =================================================================================
// tf32x3 GEMM:  C = alpha*A (@) B  (TRANS_B ? A@B^T : A@B), fp32 in/out.
// Split each operand into (hi, lo) tf32 parts at SMEM-store time; accumulate
// hi*hi + hi*lo + lo*hi in fp32 -> ~fp32 accuracy.
// Block tile 128x128, K-tile 16. 256 threads = 8 warps, each warp 64x32 via
// 4x2 wmma m16n16k8 fragments. Batched via blockIdx.z with element strides.
// Register-prefetch pipeline: next K-tile's gmem loads are issued before the
// current tile's MMA work, hiding DRAM/L2 latency behind tensor ops.
// All dims assumed multiples of tile sizes (true for this problem).
// =================================================================================
template <bool TRANS_B>
__global__ __launch_bounds__(256) void gemm_tf32x3(
    const float* __restrict__ A, const float* __restrict__ B, float* __restrict__ C,
    int M, int N, int K, int lda, int ldb, int ldc,
    long long sA, long long sB, long long sC, float alpha)
{
    constexpr int BM = 128, BN = 128, BK = 16, PAD = 4;
    constexpr int B0 = TRANS_B ? BN : BK;
    constexpr int B1 = TRANS_B ? (BK + PAD) : (BN + PAD);

    __shared__ __align__(16) float Ah[BM][BK + PAD];
    __shared__ __align__(16) float Al[BM][BK + PAD];
    __shared__ __align__(16) float Bh[B0][B1];
    __shared__ __align__(16) float Bl[B0][B1];

    const float* Ab = A + (size_t)blockIdx.z * (size_t)sA;
    const float* Bb = B + (size_t)blockIdx.z * (size_t)sB;
    float*       Cb = C + (size_t)blockIdx.z * (size_t)sC;

    const int m0  = blockIdx.y * BM;
    const int n0  = blockIdx.x * BN;
    const int tid = threadIdx.x;
    const int warp = tid >> 5;
    const int wm = warp & 1;   // 2 warps along M (64 rows each)
    const int wn = warp >> 1;  // 4 warps along N (32 cols each)

    // per-thread load coordinates (fixed across K iterations)
    const int a_row0 = tid >> 2,               a_c4 = (tid & 3) << 2;            // + it*64 rows
    int b_row0, b_c4;
    if constexpr (TRANS_B) { b_row0 = tid >> 2; b_c4 = (tid & 3) << 2; }         // n, k ; + it*64 rows
    else                   { b_row0 = tid >> 5; b_c4 = (tid & 31) << 2; }        // k, n ; + it*8 rows

    wmma::fragment<wmma::accumulator, 16, 16, 8, float> acc[4][2];
#pragma unroll
    for (int i = 0; i < 4; i++)
#pragma unroll
        for (int j = 0; j < 2; j++) wmma::fill_fragment(acc[i][j], 0.0f);

    using BLayout = typename std::conditional<TRANS_B, wmma::col_major, wmma::row_major>::type;

    float4 pa[2], pb[2];

    // ---- prologue: load K-tile 0 into registers ----
#pragma unroll
    for (int it = 0; it < 2; ++it) {
        pa[it] = *reinterpret_cast<const float4*>(&Ab[(size_t)(m0 + a_row0 + it * 64) * lda + a_c4]);
        if constexpr (TRANS_B)
            pb[it] = *reinterpret_cast<const float4*>(&Bb[(size_t)(n0 + b_row0 + it * 64) * ldb + b_c4]);
        else
            pb[it] = *reinterpret_cast<const float4*>(&Bb[(size_t)(b_row0 + it * 8) * ldb + n0 + b_c4]);
    }

    for (int k0 = 0; k0 < K; k0 += BK) {
        // ---- store current registers into smem with tf32 hi/lo split ----
#pragma unroll
        for (int it = 0; it < 2; ++it) {
            int row = a_row0 + it * 64;
            float vv[4] = {pa[it].x, pa[it].y, pa[it].z, pa[it].w};
#pragma unroll
            for (int q = 0; q < 4; q++) {
                float x  = vv[q] * alpha;
                float hi = to_tf32(x);
                Ah[row][a_c4 + q] = hi;
                Al[row][a_c4 + q] = to_tf32(x - hi);
            }
        }
#pragma unroll
        for (int it = 0; it < 2; ++it) {
            float vv[4] = {pb[it].x, pb[it].y, pb[it].z, pb[it].w};
            int row = TRANS_B ? (b_row0 + it * 64) : (b_row0 + it * 8);
#pragma unroll
            for (int q = 0; q < 4; q++) {
                float hi = to_tf32(vv[q]);
                Bh[row][b_c4 + q] = hi;
                Bl[row][b_c4 + q] = to_tf32(vv[q] - hi);
            }
        }
        __syncthreads();

        // ---- prefetch next K-tile into registers (overlaps with MMA below) ----
        const int kn = k0 + BK;
        if (kn < K) {
#pragma unroll
            for (int it = 0; it < 2; ++it) {
                pa[it] = *reinterpret_cast<const float4*>(&Ab[(size_t)(m0 + a_row0 + it * 64) * lda + kn + a_c4]);
                if constexpr (TRANS_B)
                    pb[it] = *reinterpret_cast<const float4*>(&Bb[(size_t)(n0 + b_row0 + it * 64) * ldb + kn + b_c4]);
                else
                    pb[it] = *reinterpret_cast<const float4*>(&Bb[(size_t)(kn + b_row0 + it * 8) * ldb + n0 + b_c4]);
            }
        }

        // ---- MMA on current smem tiles ----
#pragma unroll
        for (int kk = 0; kk < BK; kk += 8) {
            wmma::fragment<wmma::matrix_a, 16, 16, 8, wmma::precision::tf32, wmma::row_major> ah[4], al[4];
            wmma::fragment<wmma::matrix_b, 16, 16, 8, wmma::precision::tf32, BLayout> bh[2], bl[2];
#pragma unroll
            for (int i = 0; i < 4; i++) {
                wmma::load_matrix_sync(ah[i], &Ah[wm * 64 + i * 16][kk], BK + PAD);
                wmma::load_matrix_sync(al[i], &Al[wm * 64 + i * 16][kk], BK + PAD);
            }
#pragma unroll
            for (int j = 0; j < 2; j++) {
                if constexpr (TRANS_B) {
                    wmma::load_matrix_sync(bh[j], &Bh[wn * 32 + j * 16][kk], B1);
                    wmma::load_matrix_sync(bl[j], &Bl[wn * 32 + j * 16][kk], B1);
                } else {
                    wmma::load_matrix_sync(bh[j], &Bh[kk][wn * 32 + j * 16], B1);
                    wmma::load_matrix_sync(bl[j], &Bl[kk][wn * 32 + j * 16], B1);
                }
            }
#pragma unroll
            for (int i = 0; i < 4; i++)
#pragma unroll
                for (int j = 0; j < 2; j++) {
                    wmma::mma_sync(acc[i][j], ah[i], bh[j], acc[i][j]);
                    wmma::mma_sync(acc[i][j], al[i], bh[j], acc[i][j]);
                    wmma::mma_sync(acc[i][j], ah[i], bl[j], acc[i][j]);
                }
        }
        __syncthreads();
    }

#pragma unroll
    for (int i = 0; i < 4; i++)
#pragma unroll
        for (int j = 0; j < 2; j++)
            wmma::store_matrix_sync(&Cb[(size_t)(m0 + wm * 64 + i * 16) * ldc + n0 + wn * 32 + j * 16],
                                    acc[i][j], ldc, wmma::mem_row_major);
}

// =================================================================================
// bias + RoPE fused (rope_dim == head_dim == 128, half = 64).
// Matches reference numerics: fp32 inv_freq, fp32 angle = s * inv_freq, sincosf.
// One thread per rotated pair: 2048 rows * 16 heads * 64 pairs = 2M threads.
// =================================================================================
__global__ __launch_bounds__(256) void rope_bias_kernel(float* __restrict__ Xm,
                                                        const float* __restrict__ bias)
{
    int idx = blockIdx.x * blockDim.x + threadIdx.x;
    if (idx >= S_DIM * NHEAD * 64) return;
    int s = idx >> 10;        // / (16*64)
    int r = idx & 1023;
    int h = r >> 6;
    int d = r & 63;
    int c1 = h * HD + d;
    int c2 = c1 + 64;
    size_t o = (size_t)s * H_DIM;

    float x1 = Xm[o + c1] + bias[c1];
    float x2 = Xm[o + c2] + bias[c2];

    float e    = (float)d * (1.0f / 64.0f);                       // exact
    float invf = (float)exp(-(double)e * 9.210340371976184);      // ln(10000)
    float ang  = (float)s * invf;                                 // fp32, like ref
    float sn, cs;
    sincosf(ang, &sn, &cs);

    Xm[o + c1] = x1 * cs - x2 * sn;
    Xm[o + c2] = x2 * cs + x1 * sn;
}

__global__ __launch_bounds__(256) void add_bias_kernel(float* __restrict__ C,
                                                       const float* __restrict__ b, int total)
{
    int idx = blockIdx.x * blockDim.x + threadIdx.x;
    if (idx < total) C[idx] += b[idx & (H_DIM - 1)];
}

// =================================================================================
// Row softmax over 2048 elements, one block (256 threads) per row, in place.
// =================================================================================
__global__ __launch_bounds__(256) void softmax_rows(float* __restrict__ Sc)
{
    size_t base = (size_t)blockIdx.x * S_DIM;
    int tid = threadIdx.x;
    __shared__ float red[32];

    float v[8];
    float m = -3.402823e38f;
#pragma unroll
    for (int i = 0; i < 8; i++) {
        v[i] = Sc[base + tid + (i << 8)];
        m = fmaxf(m, v[i]);
    }
#pragma unroll
    for (int o = 16; o > 0; o >>= 1) m = fmaxf(m, __shfl_xor_sync(0xffffffffu, m, o));
    if ((tid & 31) == 0) red[tid >> 5] = m;
    __syncthreads();
    if (tid < 32) {
        float bm = (tid < 8) ? red[tid] : -3.402823e38f;
#pragma unroll
        for (int o = 4; o > 0; o >>= 1) bm = fmaxf(bm, __shfl_xor_sync(0xffffffffu, bm, o));
        if (tid == 0) red[0] = bm;
    }
    __syncthreads();
    m = red[0];

    float s = 0.f;
#pragma unroll
    for (int i = 0; i < 8; i++) {
        v[i] = expf(v[i] - m);
        s += v[i];
    }
    __syncthreads();  // protect red reuse
#pragma unroll
    for (int o = 16; o > 0; o >>= 1) s += __shfl_xor_sync(0xffffffffu, s, o);
    if ((tid & 31) == 0) red[tid >> 5] = s;
    __syncthreads();
    if (tid < 32) {
        float bs = (tid < 8) ? red[tid] : 0.f;
#pragma unroll
        for (int o = 4; o > 0; o >>= 1) bs += __shfl_xor_sync(0xffffffffu, bs, o);
        if (tid == 0) red[0] = bs;
    }
    __syncthreads();
    float inv = 1.0f / red[0];
#pragma unroll
    for (int i = 0; i < 8; i++) Sc[base + tid + (i << 8)] = v[i] * inv;
}

// =================================================================================
// launch
// =================================================================================
extern "C" void kernel_launch(void* const* d_in, const int* in_sizes, int n_in,
                              void* d_out, int out_size)
{
    const float* X  = (const float*)d_in[0];
    const float* wq = (const float*)d_in[1];
    const float* bq = (const float*)d_in[2];
    const float* wk = (const float*)d_in[3];
    const float* bk = (const float*)d_in[4];
    const float* wv = (const float*)d_in[5];
    const float* bv = (const float*)d_in[6];
    const float* wo = (const float*)d_in[7];
    const float* bo = (const float*)d_in[8];
    float* out = (float*)d_out;

    float* Q = nullptr; float* K = nullptr; float* V = nullptr;
    float* ATT = nullptr; float* SCR = nullptr;
    cudaGetSymbolAddress((void**)&Q,   g_Q);
    cudaGetSymbolAddress((void**)&K,   g_K);
    cudaGetSymbolAddress((void**)&V,   g_V);
    cudaGetSymbolAddress((void**)&ATT, g_attn);
    cudaGetSymbolAddress((void**)&SCR, g_scores);

    const int TPB = 256;
    const long long SS = (long long)S_DIM * S_DIM;
    const float inv_sqrt_hd = 0.08838834764831845f;  // 1/sqrt(128)

    // 1) projections
    dim3 gFull(H_DIM / 128, S_DIM / 128, 1);
    gemm_tf32x3<false><<<gFull, TPB>>>(X, wq, Q, S_DIM, H_DIM, H_DIM, H_DIM, H_DIM, H_DIM, 0, 0, 0, 1.0f);
    gemm_tf32x3<false><<<gFull, TPB>>>(X, wk, K, S_DIM, H_DIM, H_DIM, H_DIM, H_DIM, H_DIM, 0, 0, 0, 1.0f);
    gemm_tf32x3<false><<<gFull, TPB>>>(X, wv, V, S_DIM, H_DIM, H_DIM, H_DIM, H_DIM, H_DIM, 0, 0, 0, 1.0f);

    // 2) bias + rope on Q,K ; bias on V
    int ropeN = S_DIM * NHEAD * 64;
    rope_bias_kernel<<<(ropeN + TPB - 1) / TPB, TPB>>>(Q, bq);
    rope_bias_kernel<<<(ropeN + TPB - 1) / TPB, TPB>>>(K, bk);
    add_bias_kernel<<<(S_DIM * H_DIM + TPB - 1) / TPB, TPB>>>(V, bv, S_DIM * H_DIM);

    // 3) scores[h] = (Q_h / sqrt(hd)) @ K_h^T    (batched over heads)
    dim3 gScores(S_DIM / 128, S_DIM / 128, NHEAD);
    gemm_tf32x3<true><<<gScores, TPB>>>(Q, K, SCR, S_DIM, S_DIM, HD,
                                        H_DIM, H_DIM, S_DIM,
                                        HD, HD, SS, inv_sqrt_hd);

    // 4) softmax over keys
    softmax_rows<<<NHEAD * S_DIM, TPB>>>(SCR);

    // 5) attn[h] = P_h @ V_h
    dim3 gPV(HD / 128, S_DIM / 128, NHEAD);
    gemm_tf32x3<false><<<gPV, TPB>>>(SCR, V, ATT, S_DIM, HD, S_DIM,
                                     S_DIM, H_DIM, H_DIM,
                                     SS, HD, HD, 1.0f);

    // 6) out = attn @ wo + bo
    gemm_tf32x3<false><<<gFull, TPB>>>(ATT, wo, out, S_DIM, H_DIM, H_DIM, H_DIM, H_DIM, H_DIM, 0, 0, 0, 1.0f);
    add_bias_kernel<<<(S_DIM * H_DIM + TPB - 1) / TPB, TPB>>>(out, bo, S_DIM * H_DIM);
}

// round 8
// speedup vs baseline: 3.0593x; 3.0593x over previous
#include <cuda_runtime.h>
#include <cuda_bf16.h>
#include <mma.h>
#include <math.h>
#include <stdint.h>

using namespace nvcuda;

#define S_DIM 2048
#define H_DIM 2048
#define NHEAD 16
#define HD    128
typedef __nv_bfloat16 bf16;

// ---------------- scratch (static device globals; no allocation) ----------------
#define ELEM_SQ ((size_t)2048 * 2048)
__device__ bf16 g_Xh[ELEM_SQ],  g_Xl[ELEM_SQ];
__device__ bf16 g_WTh[ELEM_SQ], g_WTl[ELEM_SQ];
__device__ bf16 g_Qh[ELEM_SQ],  g_Ql[ELEM_SQ];
__device__ bf16 g_Kh[ELEM_SQ],  g_Kl[ELEM_SQ];
__device__ bf16 g_VTh[ELEM_SQ], g_VTl[ELEM_SQ];
__device__ bf16 g_ATTh[ELEM_SQ],g_ATTl[ELEM_SQ];
__device__ bf16 g_Ph[(size_t)NHEAD * ELEM_SQ], g_Pl[(size_t)NHEAD * ELEM_SQ];
__device__ float g_scores[(size_t)NHEAD * ELEM_SQ];
__device__ float g_f32tmp[ELEM_SQ];

__device__ __forceinline__ uint32_t s2u(const void* p) {
    uint32_t a;
    asm("{ .reg .u64 t; cvta.to.shared.u64 t, %1; cvt.u32.u64 %0, t; }" : "=r"(a) : "l"(p));
    return a;
}
__device__ __forceinline__ void cpa16(uint32_t saddr, const void* gaddr) {
    asm volatile("cp.async.cg.shared.global [%0], [%1], 16;" :: "r"(saddr), "l"(gaddr));
}
#define CPA_COMMIT() asm volatile("cp.async.commit_group;" ::: "memory")
#define CPA_WAIT(n)  asm volatile("cp.async.wait_group %0;" :: "n"(n) : "memory")

// smem layout: 2 stages x (Ah, Al, Bh, Bl), each array 128 rows x (32+8) bf16 = 10240 B
static constexpr int ARR_B   = 10240;   // 128 * 40 * 2
static constexpr int STAGE_B = 4 * ARR_B;
static constexpr int SMEM_DYN = 2 * STAGE_B;  // 81920
static constexpr int LDP = 40;          // padded leading dim (bf16 elems)

// =================================================================================
// bf16x3 wmma GEMM:  C[m][n] = sum_k A[m][k]*B[n][k]   (always A·B^T, K-major ops)
// A=(Ah+Al), B=(Bh+Bl) bf16 hi/lo splits of fp32; acc = AhBh + AhBl + AlBh in fp32.
// 128x128 CTA tile, BK=32, 2-stage cp.async pipeline. 8 warps -> 64x32 each via
// 4x2 m16n16k16 fragments. Batched via blockIdx.z with element strides.
// =================================================================================
__global__ void __launch_bounds__(256)
gemm_bf16x3(const bf16* __restrict__ Ah, const bf16* __restrict__ Al,
            const bf16* __restrict__ Bh, const bf16* __restrict__ Bl,
            float* __restrict__ C, int K, int lda, int ldb, int ldc,
            long long sA, long long sB, long long sC)
{
    extern __shared__ char dbuf[];
    const uint32_t smemu = s2u(dbuf);

    const int tid = threadIdx.x, warp = tid >> 5;
    const int wm = warp & 1, wn = warp >> 1;
    const int m0 = blockIdx.y * 128, n0 = blockIdx.x * 128;

    const bf16* Abh = Ah + (size_t)blockIdx.z * sA;
    const bf16* Abl = Al + (size_t)blockIdx.z * sA;
    const bf16* Bbh = Bh + (size_t)blockIdx.z * sB;
    const bf16* Bbl = Bl + (size_t)blockIdx.z * sB;
    float*      Cb  = C  + (size_t)blockIdx.z * sC;

    // per-thread cp.async chunks: 512 16B-chunks per array, 2 per thread per array
    int row_[2], c_[2];
#pragma unroll
    for (int i = 0; i < 2; i++) {
        int chunk = tid + 256 * i;
        row_[i] = chunk >> 2;
        c_[i]   = chunk & 3;
    }

    wmma::fragment<wmma::accumulator, 16, 16, 16, float> acc[4][2];
#pragma unroll
    for (int i = 0; i < 4; i++)
#pragma unroll
        for (int j = 0; j < 2; j++) wmma::fill_fragment(acc[i][j], 0.0f);

    const int nt = K >> 5;   // K / 32

    // prologue: stage 0 <- tile 0
#pragma unroll
    for (int i = 0; i < 2; i++) {
        uint32_t so = (uint32_t)(row_[i] * (LDP * 2) + c_[i] * 16);
        size_t ao = (size_t)(m0 + row_[i]) * lda + c_[i] * 8;
        size_t bo = (size_t)(n0 + row_[i]) * ldb + c_[i] * 8;
        cpa16(smemu + so,             Abh + ao);
        cpa16(smemu + ARR_B + so,     Abl + ao);
        cpa16(smemu + 2 * ARR_B + so, Bbh + bo);
        cpa16(smemu + 3 * ARR_B + so, Bbl + bo);
    }
    CPA_COMMIT();

    for (int t = 0; t < nt; t++) {
        if (t + 1 < nt) {   // issue next tile into other stage
            uint32_t sb = smemu + ((t + 1) & 1) * STAGE_B;
            int k0 = (t + 1) << 5;
#pragma unroll
            for (int i = 0; i < 2; i++) {
                uint32_t so = (uint32_t)(row_[i] * (LDP * 2) + c_[i] * 16);
                size_t ao = (size_t)(m0 + row_[i]) * lda + k0 + c_[i] * 8;
                size_t bo = (size_t)(n0 + row_[i]) * ldb + k0 + c_[i] * 8;
                cpa16(sb + so,             Abh + ao);
                cpa16(sb + ARR_B + so,     Abl + ao);
                cpa16(sb + 2 * ARR_B + so, Bbh + bo);
                cpa16(sb + 3 * ARR_B + so, Bbl + bo);
            }
            CPA_COMMIT();
            CPA_WAIT(1);
        } else {
            CPA_WAIT(0);
        }
        __syncthreads();

        const char* st = dbuf + (t & 1) * STAGE_B;
        const bf16* sAh = reinterpret_cast<const bf16*>(st);
        const bf16* sAl = reinterpret_cast<const bf16*>(st + ARR_B);
        const bf16* sBh = reinterpret_cast<const bf16*>(st + 2 * ARR_B);
        const bf16* sBl = reinterpret_cast<const bf16*>(st + 3 * ARR_B);

#pragma unroll
        for (int ks = 0; ks < 2; ks++) {
            const int kk = ks * 16;
            wmma::fragment<wmma::matrix_a, 16, 16, 16, bf16, wmma::row_major> ah[4], al[4];
            wmma::fragment<wmma::matrix_b, 16, 16, 16, bf16, wmma::col_major> bh[2], bl[2];
#pragma unroll
            for (int i = 0; i < 4; i++) {
                wmma::load_matrix_sync(ah[i], sAh + (wm * 64 + i * 16) * LDP + kk, LDP);
                wmma::load_matrix_sync(al[i], sAl + (wm * 64 + i * 16) * LDP + kk, LDP);
            }
#pragma unroll
            for (int j = 0; j < 2; j++) {
                wmma::load_matrix_sync(bh[j], sBh + (wn * 32 + j * 16) * LDP + kk, LDP);
                wmma::load_matrix_sync(bl[j], sBl + (wn * 32 + j * 16) * LDP + kk, LDP);
            }
#pragma unroll
            for (int i = 0; i < 4; i++)
#pragma unroll
                for (int j = 0; j < 2; j++) {
                    wmma::mma_sync(acc[i][j], ah[i], bh[j], acc[i][j]);
                    wmma::mma_sync(acc[i][j], al[i], bh[j], acc[i][j]);
                    wmma::mma_sync(acc[i][j], ah[i], bl[j], acc[i][j]);
                }
        }
        __syncthreads();
    }

#pragma unroll
    for (int i = 0; i < 4; i++)
#pragma unroll
        for (int j = 0; j < 2; j++)
            wmma::store_matrix_sync(&Cb[(size_t)(m0 + wm * 64 + i * 16) * ldc + n0 + wn * 32 + j * 16],
                                    acc[i][j], ldc, wmma::mem_row_major);
}

// ---------------- bf16 hi/lo split helpers ----------------
__device__ __forceinline__ void split1(float x, uint16_t& h, uint16_t& l) {
    bf16 hb = __float2bfloat16_rn(x);
    float r = x - __bfloat162float(hb);
    bf16 lb = __float2bfloat16_rn(r);
    h = *reinterpret_cast<uint16_t*>(&hb);
    l = *reinterpret_cast<uint16_t*>(&lb);
}

// split fp32 -> (hi, lo) bf16, same layout
__global__ void __launch_bounds__(256) conv_split(const float* __restrict__ in,
                                                  bf16* __restrict__ oh, bf16* __restrict__ ol,
                                                  int n4)
{
    int i = blockIdx.x * blockDim.x + threadIdx.x;
    if (i >= n4) return;
    float4 v = reinterpret_cast<const float4*>(in)[i];
    uint16_t h0, l0, h1, l1, h2, l2, h3, l3;
    split1(v.x, h0, l0); split1(v.y, h1, l1); split1(v.z, h2, l2); split1(v.w, h3, l3);
    uint2 H = make_uint2((uint32_t)h0 | ((uint32_t)h1 << 16), (uint32_t)h2 | ((uint32_t)h3 << 16));
    uint2 L = make_uint2((uint32_t)l0 | ((uint32_t)l1 << 16), (uint32_t)l2 | ((uint32_t)l3 << 16));
    reinterpret_cast<uint2*>(oh)[i] = H;
    reinterpret_cast<uint2*>(ol)[i] = L;
}

// out[n][k] = in[k][n] (+ bias[n]), split into bf16 hi/lo.  2048x2048.
__global__ void __launch_bounds__(256) transpose_split(const float* __restrict__ in,
                                                       const float* __restrict__ bias,
                                                       bf16* __restrict__ oh, bf16* __restrict__ ol)
{
    __shared__ float t[32][33];
    int tx = threadIdx.x & 31, ty = threadIdx.x >> 5;
    int bx = blockIdx.x, by = blockIdx.y;
    int xin = bx * 32 + tx;
    float bv = bias ? bias[xin] : 0.0f;
#pragma unroll
    for (int j = 0; j < 4; j++) {
        int yin = by * 32 + ty + j * 8;
        t[ty + j * 8][tx] = in[(size_t)yin * H_DIM + xin] + bv;
    }
    __syncthreads();
#pragma unroll
    for (int j = 0; j < 4; j++) {
        int n = bx * 32 + ty + j * 8;   // out row = input col
        int k = by * 32 + tx;           // out col = input row
        uint16_t h, l;
        split1(t[tx][ty + j * 8], h, l);
        reinterpret_cast<uint16_t*>(oh)[(size_t)n * H_DIM + k] = h;
        reinterpret_cast<uint16_t*>(ol)[(size_t)n * H_DIM + k] = l;
    }
}

// fused bias + RoPE + scale + bf16 hi/lo split (rope_dim == head_dim == 128)
__global__ void __launch_bounds__(256) rope_conv(const float* __restrict__ in,
                                                 const float* __restrict__ bias,
                                                 bf16* __restrict__ oh, bf16* __restrict__ ol,
                                                 float scale)
{
    __shared__ float tinv[64];
    int tid = threadIdx.x;
    if (tid < 64)
        tinv[tid] = (float)exp(-(double)tid * (9.210340371976184 / 64.0));
    __syncthreads();
    int idx = blockIdx.x * 256 + tid;   // exact: S*NHEAD*64 = 2M threads
    int s = idx >> 10;
    int r = idx & 1023;
    int h = r >> 6;
    int d = r & 63;
    int c1 = h * HD + d, c2 = c1 + 64;
    size_t o = (size_t)s * H_DIM;

    float x1 = in[o + c1] + bias[c1];
    float x2 = in[o + c2] + bias[c2];
    float ang = (float)s * tinv[d];
    float sn, cs;
    sincosf(ang, &sn, &cs);
    float r1 = (x1 * cs - x2 * sn) * scale;
    float r2 = (x2 * cs + x1 * sn) * scale;
    uint16_t h1, l1, h2, l2;
    split1(r1, h1, l1); split1(r2, h2, l2);
    reinterpret_cast<uint16_t*>(oh)[o + c1] = h1;
    reinterpret_cast<uint16_t*>(ol)[o + c1] = l1;
    reinterpret_cast<uint16_t*>(oh)[o + c2] = h2;
    reinterpret_cast<uint16_t*>(ol)[o + c2] = l2;
}

__global__ void __launch_bounds__(256) add_bias_kernel(float* __restrict__ C,
                                                       const float* __restrict__ b, int total)
{
    int idx = blockIdx.x * blockDim.x + threadIdx.x;
    if (idx < total) C[idx] += b[idx & (H_DIM - 1)];
}

// row softmax over 2048 keys + fused bf16 hi/lo split of probs
__global__ void __launch_bounds__(256) softmax_conv(const float* __restrict__ Sc,
                                                    bf16* __restrict__ Ph, bf16* __restrict__ Pl)
{
    size_t base = (size_t)blockIdx.x * S_DIM;
    int tid = threadIdx.x;
    __shared__ float red[32];

    float v[8];
    float m = -3.402823e38f;
#pragma unroll
    for (int i = 0; i < 8; i++) {
        v[i] = Sc[base + tid + (i << 8)];
        m = fmaxf(m, v[i]);
    }
#pragma unroll
    for (int o = 16; o > 0; o >>= 1) m = fmaxf(m, __shfl_xor_sync(0xffffffffu, m, o));
    if ((tid & 31) == 0) red[tid >> 5] = m;
    __syncthreads();
    if (tid < 32) {
        float bm = (tid < 8) ? red[tid] : -3.402823e38f;
#pragma unroll
        for (int o = 4; o > 0; o >>= 1) bm = fmaxf(bm, __shfl_xor_sync(0xffffffffu, bm, o));
        if (tid == 0) red[0] = bm;
    }
    __syncthreads();
    m = red[0];

    float s = 0.f;
#pragma unroll
    for (int i = 0; i < 8; i++) {
        v[i] = expf(v[i] - m);
        s += v[i];
    }
    __syncthreads();
#pragma unroll
    for (int o = 16; o > 0; o >>= 1) s += __shfl_xor_sync(0xffffffffu, s, o);
    if ((tid & 31) == 0) red[tid >> 5] = s;
    __syncthreads();
    if (tid < 32) {
        float bs = (tid < 8) ? red[tid] : 0.f;
#pragma unroll
        for (int o = 4; o > 0; o >>= 1) bs += __shfl_xor_sync(0xffffffffu, bs, o);
        if (tid == 0) red[0] = bs;
    }
    __syncthreads();
    float inv = 1.0f / red[0];
#pragma unroll
    for (int i = 0; i < 8; i++) {
        float p = v[i] * inv;
        uint16_t h, l;
        split1(p, h, l);
        reinterpret_cast<uint16_t*>(Ph)[base + tid + (i << 8)] = h;
        reinterpret_cast<uint16_t*>(Pl)[base + tid + (i << 8)] = l;
    }
}

// =================================================================================
// launch
// =================================================================================
extern "C" void kernel_launch(void* const* d_in, const int* in_sizes, int n_in,
                              void* d_out, int out_size)
{
    const float* X  = (const float*)d_in[0];
    const float* wq = (const float*)d_in[1];
    const float* bq = (const float*)d_in[2];
    const float* wk = (const float*)d_in[3];
    const float* bk = (const float*)d_in[4];
    const float* wv = (const float*)d_in[5];
    const float* bv = (const float*)d_in[6];
    const float* wo = (const float*)d_in[7];
    const float* bo = (const float*)d_in[8];
    float* out = (float*)d_out;

    bf16 *Xh, *Xl, *WTh, *WTl, *Qh, *Ql, *Kh, *Kl, *VTh, *VTl, *ATTh, *ATTl, *Ph, *Pl;
    float *SCR, *TMP;
    cudaGetSymbolAddress((void**)&Xh, g_Xh);     cudaGetSymbolAddress((void**)&Xl, g_Xl);
    cudaGetSymbolAddress((void**)&WTh, g_WTh);   cudaGetSymbolAddress((void**)&WTl, g_WTl);
    cudaGetSymbolAddress((void**)&Qh, g_Qh);     cudaGetSymbolAddress((void**)&Ql, g_Ql);
    cudaGetSymbolAddress((void**)&Kh, g_Kh);     cudaGetSymbolAddress((void**)&Kl, g_Kl);
    cudaGetSymbolAddress((void**)&VTh, g_VTh);   cudaGetSymbolAddress((void**)&VTl, g_VTl);
    cudaGetSymbolAddress((void**)&ATTh, g_ATTh); cudaGetSymbolAddress((void**)&ATTl, g_ATTl);
    cudaGetSymbolAddress((void**)&Ph, g_Ph);     cudaGetSymbolAddress((void**)&Pl, g_Pl);
    cudaGetSymbolAddress((void**)&SCR, g_scores);
    cudaGetSymbolAddress((void**)&TMP, g_f32tmp);

    cudaFuncSetAttribute(gemm_bf16x3, cudaFuncAttributeMaxDynamicSharedMemorySize, SMEM_DYN);

    const int TPB = 256;
    const long long SS  = (long long)S_DIM * S_DIM;
    const long long SVB = (long long)HD * S_DIM;
    dim3 tgrid(64, 64, 1);
    dim3 gFull(16, 16, 1);

    // X -> bf16 hi/lo
    conv_split<<<4096, TPB>>>(X, Xh, Xl, S_DIM * H_DIM / 4);

    // Q = X @ wq ; bias + rope + scale(1/sqrt(hd)) + split
    transpose_split<<<tgrid, TPB>>>(wq, nullptr, WTh, WTl);
    gemm_bf16x3<<<gFull, TPB, SMEM_DYN>>>(Xh, Xl, WTh, WTl, TMP, H_DIM, H_DIM, H_DIM, H_DIM, 0, 0, 0);
    rope_conv<<<8192, TPB>>>(TMP, bq, Qh, Ql, 0.08838834764831845f);

    // K
    transpose_split<<<tgrid, TPB>>>(wk, nullptr, WTh, WTl);
    gemm_bf16x3<<<gFull, TPB, SMEM_DYN>>>(Xh, Xl, WTh, WTl, TMP, H_DIM, H_DIM, H_DIM, H_DIM, 0, 0, 0);
    rope_conv<<<8192, TPB>>>(TMP, bk, Kh, Kl, 1.0f);

    // V (bias folded into the transpose): VT[h*128+d][s] = V[s][h*128+d] + bv
    transpose_split<<<tgrid, TPB>>>(wv, nullptr, WTh, WTl);
    gemm_bf16x3<<<gFull, TPB, SMEM_DYN>>>(Xh, Xl, WTh, WTl, TMP, H_DIM, H_DIM, H_DIM, H_DIM, 0, 0, 0);
    transpose_split<<<tgrid, TPB>>>(TMP, bv, VTh, VTl);

    // scores[h] = Qs_h @ K_h^T   (A rows=q, B rows=s, K=128 head dim)
    dim3 gScores(16, 16, NHEAD);
    gemm_bf16x3<<<gScores, TPB, SMEM_DYN>>>(Qh, Ql, Kh, Kl, SCR, HD,
                                            H_DIM, H_DIM, S_DIM,
                                            HD, HD, SS);

    // softmax + split probs to bf16
    softmax_conv<<<NHEAD * S_DIM, TPB>>>(SCR, Ph, Pl);

    // attn[h] = P_h @ V_h   (A rows=q K=s, B rows=d K=s)
    dim3 gPV(1, 16, NHEAD);
    gemm_bf16x3<<<gPV, TPB, SMEM_DYN>>>(Ph, Pl, VTh, VTl, TMP, S_DIM,
                                        S_DIM, S_DIM, H_DIM,
                                        SS, SVB, HD);

    // out = attn @ wo + bo
    conv_split<<<4096, TPB>>>(TMP, ATTh, ATTl, S_DIM * H_DIM / 4);
    transpose_split<<<tgrid, TPB>>>(wo, nullptr, WTh, WTl);
    gemm_bf16x3<<<gFull, TPB, SMEM_DYN>>>(ATTh, ATTl, WTh, WTl, out, H_DIM, H_DIM, H_DIM, H_DIM, 0, 0, 0);
    add_bias_kernel<<<(S_DIM * H_DIM + TPB - 1) / TPB, TPB>>>(out, bo, S_DIM * H_DIM);
}

// round 15
// speedup vs baseline: 3.2926x; 1.0762x over previous
#include <cuda_runtime.h>
#include <cuda_bf16.h>
#include <mma.h>
#include <math.h>
#include <stdint.h>

using namespace nvcuda;

#define S_DIM 2048
#define H_DIM 2048
#define NHEAD 16
#define HD    128
typedef __nv_bfloat16 bf16;

// ---------------- scratch (static device globals; no allocation) ----------------
#define ELEM_SQ ((size_t)2048 * 2048)
__device__ bf16 g_Xh[ELEM_SQ],  g_Xl[ELEM_SQ];
__device__ bf16 g_WTh[3 * ELEM_SQ], g_WTl[3 * ELEM_SQ];
__device__ bf16 g_Qh[ELEM_SQ],  g_Ql[ELEM_SQ];
__device__ bf16 g_Kh[ELEM_SQ],  g_Kl[ELEM_SQ];
__device__ bf16 g_VTh[ELEM_SQ], g_VTl[ELEM_SQ];
__device__ bf16 g_ATTh[ELEM_SQ],g_ATTl[ELEM_SQ];
__device__ bf16 g_Ph[(size_t)NHEAD * ELEM_SQ], g_Pl[(size_t)NHEAD * ELEM_SQ];
__device__ float g_scores[(size_t)NHEAD * ELEM_SQ];

__device__ __forceinline__ uint32_t s2u(const void* p) {
    uint32_t a;
    asm("{ .reg .u64 t; cvta.to.shared.u64 t, %1; cvt.u32.u64 %0, t; }" : "=r"(a) : "l"(p));
    return a;
}
__device__ __forceinline__ void cpa16(uint32_t saddr, const void* gaddr) {
    asm volatile("cp.async.cg.shared.global [%0], [%1], 16;" :: "r"(saddr), "l"(gaddr));
}
#define CPA_COMMIT() asm volatile("cp.async.commit_group;" ::: "memory")
#define CPA_WAIT(n)  asm volatile("cp.async.wait_group %0;" :: "n"(n) : "memory")

__device__ __forceinline__ void split1(float x, uint16_t& h, uint16_t& l) {
    bf16 hb = __float2bfloat16_rn(x);
    float r = x - __bfloat162float(hb);
    bf16 lb = __float2bfloat16_rn(r);
    h = *reinterpret_cast<uint16_t*>(&hb);
    l = *reinterpret_cast<uint16_t*>(&lb);
}

// smem: 2 stages x (Ah, Al, Bh, Bl), each array 128 rows x (32+8) bf16 = 10240 B
static constexpr int ARR_B   = 10240;
static constexpr int STAGE_B = 4 * ARR_B;
static constexpr int SMEM_DYN = 2 * STAGE_B;  // 81920 (epilogue stage 128*132*4+256 = 67840 fits)
static constexpr int LDP = 40;
static constexpr int LDE = 132;               // fp32 epilogue stage leading dim (mult of 4)

// epilogue modes
#define EPI_F32   0   // direct fp32 store (scores)
#define EPI_QKV   1   // z=0: bias+rope+scale -> O0; z=1: bias+rope -> O1; z=2: bias+transpose -> O2
#define EPI_SPLIT 2   // hi/lo split -> O0 (+ z*sC)
#define EPI_BIAS  3   // + b0 -> Cf (fp32)

// =================================================================================
// bf16x3 wmma GEMM:  C[m][n] = sum_k A[m][k]*B[n][k]  (A·B^T, K-major operands)
// acc = AhBh + AhBl + AlBh in fp32. 128x128 CTA tile, BK=32, 2-stage cp.async.
// Fused epilogues select post-processing; batched via blockIdx.z.
// =================================================================================
__global__ void __launch_bounds__(256)
gemm_epi(const bf16* __restrict__ Ah, const bf16* __restrict__ Al,
         const bf16* __restrict__ Bh, const bf16* __restrict__ Bl,
         float* __restrict__ Cf,
         bf16* __restrict__ O0h, bf16* __restrict__ O0l,
         bf16* __restrict__ O1h, bf16* __restrict__ O1l,
         bf16* __restrict__ O2h, bf16* __restrict__ O2l,
         const float* __restrict__ b0, const float* __restrict__ b1,
         const float* __restrict__ b2,
         int epi, int K, int lda, int ldb, int ldc,
         long long sA, long long sB, long long sC)
{
    extern __shared__ char dbuf[];
    const uint32_t smemu = s2u(dbuf);

    const int tid = threadIdx.x, warp = tid >> 5;
    const int wm = warp & 1, wn = warp >> 1;
    const int m0 = blockIdx.y * 128, n0 = blockIdx.x * 128;
    const int z  = blockIdx.z;

    const bf16* Abh = Ah + (size_t)z * sA;
    const bf16* Abl = Al + (size_t)z * sA;
    const bf16* Bbh = Bh + (size_t)z * sB;
    const bf16* Bbl = Bl + (size_t)z * sB;

    int row_[2], c_[2];
#pragma unroll
    for (int i = 0; i < 2; i++) {
        int chunk = tid + 256 * i;
        row_[i] = chunk >> 2;
        c_[i]   = chunk & 3;
    }

    wmma::fragment<wmma::accumulator, 16, 16, 16, float> acc[4][2];
#pragma unroll
    for (int i = 0; i < 4; i++)
#pragma unroll
        for (int j = 0; j < 2; j++) wmma::fill_fragment(acc[i][j], 0.0f);

    const int nt = K >> 5;

#pragma unroll
    for (int i = 0; i < 2; i++) {
        uint32_t so = (uint32_t)(row_[i] * (LDP * 2) + c_[i] * 16);
        size_t ao = (size_t)(m0 + row_[i]) * lda + c_[i] * 8;
        size_t bo = (size_t)(n0 + row_[i]) * ldb + c_[i] * 8;
        cpa16(smemu + so,             Abh + ao);
        cpa16(smemu + ARR_B + so,     Abl + ao);
        cpa16(smemu + 2 * ARR_B + so, Bbh + bo);
        cpa16(smemu + 3 * ARR_B + so, Bbl + bo);
    }
    CPA_COMMIT();

    for (int t = 0; t < nt; t++) {
        if (t + 1 < nt) {
            uint32_t sb = smemu + ((t + 1) & 1) * STAGE_B;
            int k0 = (t + 1) << 5;
#pragma unroll
            for (int i = 0; i < 2; i++) {
                uint32_t so = (uint32_t)(row_[i] * (LDP * 2) + c_[i] * 16);
                size_t ao = (size_t)(m0 + row_[i]) * lda + k0 + c_[i] * 8;
                size_t bo = (size_t)(n0 + row_[i]) * ldb + k0 + c_[i] * 8;
                cpa16(sb + so,             Abh + ao);
                cpa16(sb + ARR_B + so,     Abl + ao);
                cpa16(sb + 2 * ARR_B + so, Bbh + bo);
                cpa16(sb + 3 * ARR_B + so, Bbl + bo);
            }
            CPA_COMMIT();
            CPA_WAIT(1);
        } else {
            CPA_WAIT(0);
        }
        __syncthreads();

        const char* st = dbuf + (t & 1) * STAGE_B;
        const bf16* sAh = reinterpret_cast<const bf16*>(st);
        const bf16* sAl = reinterpret_cast<const bf16*>(st + ARR_B);
        const bf16* sBh = reinterpret_cast<const bf16*>(st + 2 * ARR_B);
        const bf16* sBl = reinterpret_cast<const bf16*>(st + 3 * ARR_B);

#pragma unroll
        for (int ks = 0; ks < 2; ks++) {
            const int kk = ks * 16;
            wmma::fragment<wmma::matrix_a, 16, 16, 16, bf16, wmma::row_major> ah[4], al[4];
            wmma::fragment<wmma::matrix_b, 16, 16, 16, bf16, wmma::col_major> bh[2], bl[2];
#pragma unroll
            for (int i = 0; i < 4; i++) {
                wmma::load_matrix_sync(ah[i], sAh + (wm * 64 + i * 16) * LDP + kk, LDP);
                wmma::load_matrix_sync(al[i], sAl + (wm * 64 + i * 16) * LDP + kk, LDP);
            }
#pragma unroll
            for (int j = 0; j < 2; j++) {
                wmma::load_matrix_sync(bh[j], sBh + (wn * 32 + j * 16) * LDP + kk, LDP);
                wmma::load_matrix_sync(bl[j], sBl + (wn * 32 + j * 16) * LDP + kk, LDP);
            }
#pragma unroll
            for (int i = 0; i < 4; i++)
#pragma unroll
                for (int j = 0; j < 2; j++) {
                    wmma::mma_sync(acc[i][j], ah[i], bh[j], acc[i][j]);
                    wmma::mma_sync(acc[i][j], al[i], bh[j], acc[i][j]);
                    wmma::mma_sync(acc[i][j], ah[i], bl[j], acc[i][j]);
                }
        }
        __syncthreads();
    }

    // ------------------------------ epilogues ------------------------------
    if (epi == EPI_F32) {   // direct fp32 stores (scores)
        float* Cb = Cf + (size_t)z * sC;
#pragma unroll
        for (int i = 0; i < 4; i++)
#pragma unroll
            for (int j = 0; j < 2; j++)
                wmma::store_matrix_sync(&Cb[(size_t)(m0 + wm * 64 + i * 16) * ldc + n0 + wn * 32 + j * 16],
                                        acc[i][j], ldc, wmma::mem_row_major);
        return;
    }

    // stage accumulators into smem (pipeline buffers are dead now)
    float* sm = reinterpret_cast<float*>(dbuf);
#pragma unroll
    for (int i = 0; i < 4; i++)
#pragma unroll
        for (int j = 0; j < 2; j++)
            wmma::store_matrix_sync(&sm[(wm * 64 + i * 16) * LDE + wn * 32 + j * 16],
                                    acc[i][j], LDE, wmma::mem_row_major);
    float* tinv = reinterpret_cast<float*>(dbuf + 128 * LDE * 4);
    if (epi == EPI_QKV && z < 2 && tid < 64)
        tinv[tid] = (float)exp(-(double)tid * (9.210340371976184 / 64.0));
    __syncthreads();

    if (epi == EPI_QKV) {
        if (z < 2) {        // Q (z=0) / K (z=1): bias + rope (+ scale for Q) + split
            const float* bias = z ? b1 : b0;
            bf16* oh = z ? O1h : O0h;
            bf16* ol = z ? O1l : O0l;
            const float scale = z ? 1.0f : 0.08838834764831845f;
#pragma unroll
            for (int i = 0; i < 32; i++) {
                int p = tid + (i << 8);          // 0..8191 pairs
                int d = p & 63, row = p >> 6;
                float x1 = sm[row * LDE + d]      + bias[n0 + d];
                float x2 = sm[row * LDE + d + 64] + bias[n0 + d + 64];
                float ang = (float)(m0 + row) * tinv[d];
                float sn, cs;
                sincosf(ang, &sn, &cs);
                float r1 = (x1 * cs - x2 * sn) * scale;
                float r2 = (x2 * cs + x1 * sn) * scale;
                uint16_t h1, l1, h2, l2;
                split1(r1, h1, l1); split1(r2, h2, l2);
                size_t o1 = (size_t)(m0 + row) * H_DIM + n0 + d;
                reinterpret_cast<uint16_t*>(oh)[o1]      = h1;
                reinterpret_cast<uint16_t*>(ol)[o1]      = l1;
                reinterpret_cast<uint16_t*>(oh)[o1 + 64] = h2;
                reinterpret_cast<uint16_t*>(ol)[o1 + 64] = l2;
            }
        } else {            // V: bias + transpose + split -> VT[d_global][s]
#pragma unroll
            for (int i = 0; i < 64; i++) {
                int p = tid + (i << 8);          // 0..16383
                int row = p & 127, col = p >> 7;
                float v = sm[row * LDE + col] + b2[n0 + col];
                uint16_t h, l;
                split1(v, h, l);
                size_t o = (size_t)(n0 + col) * S_DIM + m0 + row;
                reinterpret_cast<uint16_t*>(O2h)[o] = h;
                reinterpret_cast<uint16_t*>(O2l)[o] = l;
            }
        }
    } else if (epi == EPI_SPLIT) {   // PV -> ATT hi/lo
        size_t base = (size_t)z * sC;
#pragma unroll
        for (int i = 0; i < 64; i++) {
            int p = tid + (i << 8);
            int col = p & 127, row = p >> 7;
            float v = sm[row * LDE + col];
            uint16_t h, l;
            split1(v, h, l);
            size_t o = base + (size_t)(m0 + row) * ldc + n0 + col;
            reinterpret_cast<uint16_t*>(O0h)[o] = h;
            reinterpret_cast<uint16_t*>(O0l)[o] = l;
        }
    } else {                         // EPI_BIAS: out = acc + b0
        float* Cb = Cf + (size_t)z * sC;
#pragma unroll
        for (int i = 0; i < 64; i++) {
            int p = tid + (i << 8);
            int col = p & 127, row = p >> 7;
            Cb[(size_t)(m0 + row) * ldc + n0 + col] = sm[row * LDE + col] + b0[n0 + col];
        }
    }
}

// split fp32 -> (hi, lo) bf16, same layout
__global__ void __launch_bounds__(256) conv_split(const float* __restrict__ in,
                                                  bf16* __restrict__ oh, bf16* __restrict__ ol,
                                                  int n4)
{
    int i = blockIdx.x * blockDim.x + threadIdx.x;
    if (i >= n4) return;
    float4 v = reinterpret_cast<const float4*>(in)[i];
    uint16_t h0, l0, h1, l1, h2, l2, h3, l3;
    split1(v.x, h0, l0); split1(v.y, h1, l1); split1(v.z, h2, l2); split1(v.w, h3, l3);
    uint2 H = make_uint2((uint32_t)h0 | ((uint32_t)h1 << 16), (uint32_t)h2 | ((uint32_t)h3 << 16));
    uint2 L = make_uint2((uint32_t)l0 | ((uint32_t)l1 << 16), (uint32_t)l2 | ((uint32_t)l3 << 16));
    reinterpret_cast<uint2*>(oh)[i] = H;
    reinterpret_cast<uint2*>(ol)[i] = L;
}

// out[n][k] = in[k][n], split into bf16 hi/lo.  2048x2048.
__global__ void __launch_bounds__(256) transpose_split(const float* __restrict__ in,
                                                       bf16* __restrict__ oh, bf16* __restrict__ ol)
{
    __shared__ float t[32][33];
    int tx = threadIdx.x & 31, ty = threadIdx.x >> 5;
    int bx = blockIdx.x, by = blockIdx.y;
    int xin = bx * 32 + tx;
#pragma unroll
    for (int j = 0; j < 4; j++) {
        int yin = by * 32 + ty + j * 8;
        t[ty + j * 8][tx] = in[(size_t)yin * H_DIM + xin];
    }
    __syncthreads();
#pragma unroll
    for (int j = 0; j < 4; j++) {
        int n = bx * 32 + ty + j * 8;
        int k = by * 32 + tx;
        uint16_t h, l;
        split1(t[tx][ty + j * 8], h, l);
        reinterpret_cast<uint16_t*>(oh)[(size_t)n * H_DIM + k] = h;
        reinterpret_cast<uint16_t*>(ol)[(size_t)n * H_DIM + k] = l;
    }
}

// row softmax over 2048 keys + fused bf16 hi/lo split of probs
__global__ void __launch_bounds__(256) softmax_conv(const float* __restrict__ Sc,
                                                    bf16* __restrict__ Ph, bf16* __restrict__ Pl)
{
    size_t base = (size_t)blockIdx.x * S_DIM;
    int tid = threadIdx.x;
    __shared__ float red[32];

    float v[8];
    float m = -3.402823e38f;
#pragma unroll
    for (int i = 0; i < 8; i++) {
        v[i] = Sc[base + tid + (i << 8)];
        m = fmaxf(m, v[i]);
    }
#pragma unroll
    for (int o = 16; o > 0; o >>= 1) m = fmaxf(m, __shfl_xor_sync(0xffffffffu, m, o));
    if ((tid & 31) == 0) red[tid >> 5] = m;
    __syncthreads();
    if (tid < 32) {
        float bm = (tid < 8) ? red[tid] : -3.402823e38f;
#pragma unroll
        for (int o = 4; o > 0; o >>= 1) bm = fmaxf(bm, __shfl_xor_sync(0xffffffffu, bm, o));
        if (tid == 0) red[0] = bm;
    }
    __syncthreads();
    m = red[0];

    float s = 0.f;
#pragma unroll
    for (int i = 0; i < 8; i++) {
        v[i] = expf(v[i] - m);
        s += v[i];
    }
    __syncthreads();
#pragma unroll
    for (int o = 16; o > 0; o >>= 1) s += __shfl_xor_sync(0xffffffffu, s, o);
    if ((tid & 31) == 0) red[tid >> 5] = s;
    __syncthreads();
    if (tid < 32) {
        float bs = (tid < 8) ? red[tid] : 0.f;
#pragma unroll
        for (int o = 4; o > 0; o >>= 1) bs += __shfl_xor_sync(0xffffffffu, bs, o);
        if (tid == 0) red[0] = bs;
    }
    __syncthreads();
    float inv = 1.0f / red[0];
#pragma unroll
    for (int i = 0; i < 8; i++) {
        float p = v[i] * inv;
        uint16_t h, l;
        split1(p, h, l);
        reinterpret_cast<uint16_t*>(Ph)[base + tid + (i << 8)] = h;
        reinterpret_cast<uint16_t*>(Pl)[base + tid + (i << 8)] = l;
    }
}

// =================================================================================
// launch
// =================================================================================
extern "C" void kernel_launch(void* const* d_in, const int* in_sizes, int n_in,
                              void* d_out, int out_size)
{
    const float* X  = (const float*)d_in[0];
    const float* wq = (const float*)d_in[1];
    const float* bq = (const float*)d_in[2];
    const float* wk = (const float*)d_in[3];
    const float* bk = (const float*)d_in[4];
    const float* wv = (const float*)d_in[5];
    const float* bv = (const float*)d_in[6];
    const float* wo = (const float*)d_in[7];
    const float* bo = (const float*)d_in[8];
    float* out = (float*)d_out;

    bf16 *Xh, *Xl, *WTh, *WTl, *Qh, *Ql, *Kh, *Kl, *VTh, *VTl, *ATTh, *ATTl, *Ph, *Pl;
    float *SCR;
    cudaGetSymbolAddress((void**)&Xh, g_Xh);     cudaGetSymbolAddress((void**)&Xl, g_Xl);
    cudaGetSymbolAddress((void**)&WTh, g_WTh);   cudaGetSymbolAddress((void**)&WTl, g_WTl);
    cudaGetSymbolAddress((void**)&Qh, g_Qh);     cudaGetSymbolAddress((void**)&Ql, g_Ql);
    cudaGetSymbolAddress((void**)&Kh, g_Kh);     cudaGetSymbolAddress((void**)&Kl, g_Kl);
    cudaGetSymbolAddress((void**)&VTh, g_VTh);   cudaGetSymbolAddress((void**)&VTl, g_VTl);
    cudaGetSymbolAddress((void**)&ATTh, g_ATTh); cudaGetSymbolAddress((void**)&ATTl, g_ATTl);
    cudaGetSymbolAddress((void**)&Ph, g_Ph);     cudaGetSymbolAddress((void**)&Pl, g_Pl);
    cudaGetSymbolAddress((void**)&SCR, g_scores);

    cudaFuncSetAttribute(gemm_epi, cudaFuncAttributeMaxDynamicSharedMemorySize, SMEM_DYN);

    const int TPB = 256;
    const long long SS  = (long long)S_DIM * S_DIM;
    const long long SVB = (long long)HD * S_DIM;
    dim3 tgrid(64, 64, 1);

    // X -> bf16 hi/lo
    conv_split<<<4096, TPB>>>(X, Xh, Xl, S_DIM * H_DIM / 4);

    // transpose+split all three projection weights into concatenated buffer
    transpose_split<<<tgrid, TPB>>>(wq, WTh,                WTl);
    transpose_split<<<tgrid, TPB>>>(wk, WTh + ELEM_SQ,      WTl + ELEM_SQ);
    transpose_split<<<tgrid, TPB>>>(wv, WTh + 2 * ELEM_SQ,  WTl + 2 * ELEM_SQ);

    // QKV batched GEMM with fused bias+rope+split / bias+transpose+split epilogues
    dim3 gQKV(16, 16, 3);
    gemm_epi<<<gQKV, TPB, SMEM_DYN>>>(Xh, Xl, WTh, WTl, nullptr,
                                      Qh, Ql, Kh, Kl, VTh, VTl,
                                      bq, bk, bv,
                                      EPI_QKV, H_DIM, H_DIM, H_DIM, 0,
                                      0, (long long)ELEM_SQ, 0);

    // scores[h] = Qs_h @ K_h^T  (fp32 direct store)
    dim3 gScores(16, 16, NHEAD);
    gemm_epi<<<gScores, TPB, SMEM_DYN>>>(Qh, Ql, Kh, Kl, SCR,
                                         nullptr, nullptr, nullptr, nullptr, nullptr, nullptr,
                                         nullptr, nullptr, nullptr,
                                         EPI_F32, HD, H_DIM, H_DIM, S_DIM,
                                         HD, HD, SS);

    // softmax + split probs
    softmax_conv<<<NHEAD * S_DIM, TPB>>>(SCR, Ph, Pl);

    // attn[h] = P_h @ V_h  with fused hi/lo-split epilogue -> ATT
    dim3 gPV(1, 16, NHEAD);
    gemm_epi<<<gPV, TPB, SMEM_DYN>>>(Ph, Pl, VTh, VTl, nullptr,
                                     ATTh, ATTl, nullptr, nullptr, nullptr, nullptr,
                                     nullptr, nullptr, nullptr,
                                     EPI_SPLIT, S_DIM, S_DIM, S_DIM, H_DIM,
                                     SS, SVB, HD);

    // out = attn @ wo + bo  (fused bias epilogue)
    transpose_split<<<tgrid, TPB>>>(wo, WTh, WTl);
    dim3 gOut(16, 16, 1);
    gemm_epi<<<gOut, TPB, SMEM_DYN>>>(ATTh, ATTl, WTh, WTl, out,
                                      nullptr, nullptr, nullptr, nullptr, nullptr, nullptr,
                                      bo, nullptr, nullptr,
                                      EPI_BIAS, H_DIM, H_DIM, H_DIM, H_DIM,
                                      0, 0, 0);
}

// round 16
// speedup vs baseline: 3.4951x; 1.0615x over previous
#include <cuda_runtime.h>
#include <cuda_bf16.h>
#include <mma.h>
#include <math.h>
#include <stdint.h>

using namespace nvcuda;

#define S_DIM 2048
#define H_DIM 2048
#define NHEAD 16
#define HD    128
typedef __nv_bfloat16 bf16;

// ---------------- scratch (static device globals; no allocation) ----------------
#define ELEM_SQ ((size_t)2048 * 2048)
__device__ bf16 g_Xh[ELEM_SQ],  g_Xl[ELEM_SQ];
__device__ bf16 g_WTh[3 * ELEM_SQ], g_WTl[3 * ELEM_SQ];
__device__ bf16 g_Qh[ELEM_SQ],  g_Ql[ELEM_SQ];
__device__ bf16 g_Kh[ELEM_SQ],  g_Kl[ELEM_SQ];
__device__ bf16 g_VTh[ELEM_SQ], g_VTl[ELEM_SQ];
__device__ bf16 g_ATTh[ELEM_SQ],g_ATTl[ELEM_SQ];
__device__ bf16 g_Ph[(size_t)NHEAD * ELEM_SQ], g_Pl[(size_t)NHEAD * ELEM_SQ];
__device__ float g_scores[(size_t)NHEAD * ELEM_SQ];

__device__ __forceinline__ uint32_t s2u(const void* p) {
    uint32_t a;
    asm("{ .reg .u64 t; cvta.to.shared.u64 t, %1; cvt.u32.u64 %0, t; }" : "=r"(a) : "l"(p));
    return a;
}
__device__ __forceinline__ void cpa16(uint32_t saddr, const void* gaddr) {
    asm volatile("cp.async.cg.shared.global [%0], [%1], 16;" :: "r"(saddr), "l"(gaddr));
}
#define CPA_COMMIT() asm volatile("cp.async.commit_group;" ::: "memory")
#define CPA_WAIT(n)  asm volatile("cp.async.wait_group %0;" :: "n"(n) : "memory")

__device__ __forceinline__ void split1(float x, uint16_t& h, uint16_t& l) {
    bf16 hb = __float2bfloat16_rn(x);
    float r = x - __bfloat162float(hb);
    bf16 lb = __float2bfloat16_rn(r);
    h = *reinterpret_cast<uint16_t*>(&hb);
    l = *reinterpret_cast<uint16_t*>(&lb);
}

// smem: 2 stages x (Ah, Al, Bh, Bl); BK=64: each array 128 rows x (64+8) bf16 = 18432 B
static constexpr int ARR_B   = 18432;         // 128 * 72 * 2
static constexpr int STAGE_B = 4 * ARR_B;     // 73728
static constexpr int SMEM_DYN = 2 * STAGE_B;  // 147456 (epilogue stage 128*132*4+256 = 67840 fits)
static constexpr int LDP = 72;                // padded leading dim (bf16), 144 B rows: odd*16B -> conflict-free
static constexpr int LDE = 132;               // fp32 epilogue stage leading dim

// epilogue modes
#define EPI_F32   0   // direct fp32 store (scores)
#define EPI_QKV   1   // z=0: bias+rope+scale -> O0; z=1: bias+rope -> O1; z=2: bias+transpose -> O2
#define EPI_SPLIT 2   // hi/lo split -> O0 (+ z*sC)
#define EPI_BIAS  3   // + b0 -> Cf (fp32)

// =================================================================================
// bf16x3 wmma GEMM:  C[m][n] = sum_k A[m][k]*B[n][k]  (A·B^T, K-major operands)
// acc = AhBh + AhBl + AlBh in fp32. 128x128 CTA tile, BK=64, 2-stage cp.async.
// Fused epilogues select post-processing; batched via blockIdx.z.
// =================================================================================
__global__ void __launch_bounds__(256)
gemm_epi(const bf16* __restrict__ Ah, const bf16* __restrict__ Al,
         const bf16* __restrict__ Bh, const bf16* __restrict__ Bl,
         float* __restrict__ Cf,
         bf16* __restrict__ O0h, bf16* __restrict__ O0l,
         bf16* __restrict__ O1h, bf16* __restrict__ O1l,
         bf16* __restrict__ O2h, bf16* __restrict__ O2l,
         const float* __restrict__ b0, const float* __restrict__ b1,
         const float* __restrict__ b2,
         int epi, int K, int lda, int ldb, int ldc,
         long long sA, long long sB, long long sC)
{
    extern __shared__ char dbuf[];
    const uint32_t smemu = s2u(dbuf);

    const int tid = threadIdx.x, warp = tid >> 5;
    const int wm = warp & 1, wn = warp >> 1;
    const int m0 = blockIdx.y * 128, n0 = blockIdx.x * 128;
    const int z  = blockIdx.z;

    const bf16* Abh = Ah + (size_t)z * sA;
    const bf16* Abl = Al + (size_t)z * sA;
    const bf16* Bbh = Bh + (size_t)z * sB;
    const bf16* Bbl = Bl + (size_t)z * sB;

    // per-thread cp.async chunks: 1024 16B-chunks per array (128 rows x 8), 4 per thread
    int row_[4], c_[4];
#pragma unroll
    for (int i = 0; i < 4; i++) {
        int chunk = tid + 256 * i;
        row_[i] = chunk >> 3;
        c_[i]   = chunk & 7;
    }

    wmma::fragment<wmma::accumulator, 16, 16, 16, float> acc[4][2];
#pragma unroll
    for (int i = 0; i < 4; i++)
#pragma unroll
        for (int j = 0; j < 2; j++) wmma::fill_fragment(acc[i][j], 0.0f);

    const int nt = K >> 6;   // K / 64

    // prologue: stage 0 <- tile 0
#pragma unroll
    for (int i = 0; i < 4; i++) {
        uint32_t so = (uint32_t)(row_[i] * (LDP * 2) + c_[i] * 16);
        size_t ao = (size_t)(m0 + row_[i]) * lda + c_[i] * 8;
        size_t bo = (size_t)(n0 + row_[i]) * ldb + c_[i] * 8;
        cpa16(smemu + so,             Abh + ao);
        cpa16(smemu + ARR_B + so,     Abl + ao);
        cpa16(smemu + 2 * ARR_B + so, Bbh + bo);
        cpa16(smemu + 3 * ARR_B + so, Bbl + bo);
    }
    CPA_COMMIT();

    for (int t = 0; t < nt; t++) {
        if (t + 1 < nt) {   // issue next tile into other stage
            uint32_t sb = smemu + ((t + 1) & 1) * STAGE_B;
            int k0 = (t + 1) << 6;
#pragma unroll
            for (int i = 0; i < 4; i++) {
                uint32_t so = (uint32_t)(row_[i] * (LDP * 2) + c_[i] * 16);
                size_t ao = (size_t)(m0 + row_[i]) * lda + k0 + c_[i] * 8;
                size_t bo = (size_t)(n0 + row_[i]) * ldb + k0 + c_[i] * 8;
                cpa16(sb + so,             Abh + ao);
                cpa16(sb + ARR_B + so,     Abl + ao);
                cpa16(sb + 2 * ARR_B + so, Bbh + bo);
                cpa16(sb + 3 * ARR_B + so, Bbl + bo);
            }
            CPA_COMMIT();
            CPA_WAIT(1);
        } else {
            CPA_WAIT(0);
        }
        __syncthreads();

        const char* st = dbuf + (t & 1) * STAGE_B;
        const bf16* sAh = reinterpret_cast<const bf16*>(st);
        const bf16* sAl = reinterpret_cast<const bf16*>(st + ARR_B);
        const bf16* sBh = reinterpret_cast<const bf16*>(st + 2 * ARR_B);
        const bf16* sBl = reinterpret_cast<const bf16*>(st + 3 * ARR_B);

#pragma unroll
        for (int ks = 0; ks < 4; ks++) {
            const int kk = ks * 16;
            wmma::fragment<wmma::matrix_a, 16, 16, 16, bf16, wmma::row_major> ah[4], al[4];
            wmma::fragment<wmma::matrix_b, 16, 16, 16, bf16, wmma::col_major> bh[2], bl[2];
#pragma unroll
            for (int i = 0; i < 4; i++) {
                wmma::load_matrix_sync(ah[i], sAh + (wm * 64 + i * 16) * LDP + kk, LDP);
                wmma::load_matrix_sync(al[i], sAl + (wm * 64 + i * 16) * LDP + kk, LDP);
            }
#pragma unroll
            for (int j = 0; j < 2; j++) {
                wmma::load_matrix_sync(bh[j], sBh + (wn * 32 + j * 16) * LDP + kk, LDP);
                wmma::load_matrix_sync(bl[j], sBl + (wn * 32 + j * 16) * LDP + kk, LDP);
            }
#pragma unroll
            for (int i = 0; i < 4; i++)
#pragma unroll
                for (int j = 0; j < 2; j++) {
                    wmma::mma_sync(acc[i][j], ah[i], bh[j], acc[i][j]);
                    wmma::mma_sync(acc[i][j], al[i], bh[j], acc[i][j]);
                    wmma::mma_sync(acc[i][j], ah[i], bl[j], acc[i][j]);
                }
        }
        __syncthreads();
    }

    // ------------------------------ epilogues ------------------------------
    if (epi == EPI_F32) {   // direct fp32 stores (scores)
        float* Cb = Cf + (size_t)z * sC;
#pragma unroll
        for (int i = 0; i < 4; i++)
#pragma unroll
            for (int j = 0; j < 2; j++)
                wmma::store_matrix_sync(&Cb[(size_t)(m0 + wm * 64 + i * 16) * ldc + n0 + wn * 32 + j * 16],
                                        acc[i][j], ldc, wmma::mem_row_major);
        return;
    }

    // stage accumulators into smem (pipeline buffers are dead now)
    float* sm = reinterpret_cast<float*>(dbuf);
#pragma unroll
    for (int i = 0; i < 4; i++)
#pragma unroll
        for (int j = 0; j < 2; j++)
            wmma::store_matrix_sync(&sm[(wm * 64 + i * 16) * LDE + wn * 32 + j * 16],
                                    acc[i][j], LDE, wmma::mem_row_major);
    float* tinv = reinterpret_cast<float*>(dbuf + 128 * LDE * 4);
    if (epi == EPI_QKV && z < 2 && tid < 64)
        tinv[tid] = (float)exp(-(double)tid * (9.210340371976184 / 64.0));
    __syncthreads();

    if (epi == EPI_QKV) {
        if (z < 2) {        // Q (z=0) / K (z=1): bias + rope (+ scale for Q) + split
            const float* bias = z ? b1 : b0;
            bf16* oh = z ? O1h : O0h;
            bf16* ol = z ? O1l : O0l;
            const float scale = z ? 1.0f : 0.08838834764831845f;
#pragma unroll
            for (int i = 0; i < 32; i++) {
                int p = tid + (i << 8);          // 0..8191 pairs
                int d = p & 63, row = p >> 6;
                float x1 = sm[row * LDE + d]      + bias[n0 + d];
                float x2 = sm[row * LDE + d + 64] + bias[n0 + d + 64];
                float ang = (float)(m0 + row) * tinv[d];
                float sn, cs;
                sincosf(ang, &sn, &cs);
                float r1 = (x1 * cs - x2 * sn) * scale;
                float r2 = (x2 * cs + x1 * sn) * scale;
                uint16_t h1, l1, h2, l2;
                split1(r1, h1, l1); split1(r2, h2, l2);
                size_t o1 = (size_t)(m0 + row) * H_DIM + n0 + d;
                reinterpret_cast<uint16_t*>(oh)[o1]      = h1;
                reinterpret_cast<uint16_t*>(ol)[o1]      = l1;
                reinterpret_cast<uint16_t*>(oh)[o1 + 64] = h2;
                reinterpret_cast<uint16_t*>(ol)[o1 + 64] = l2;
            }
        } else {            // V: bias + transpose + split -> VT[d_global][s]
#pragma unroll
            for (int i = 0; i < 64; i++) {
                int p = tid + (i << 8);          // 0..16383
                int row = p & 127, col = p >> 7;
                float v = sm[row * LDE + col] + b2[n0 + col];
                uint16_t h, l;
                split1(v, h, l);
                size_t o = (size_t)(n0 + col) * S_DIM + m0 + row;
                reinterpret_cast<uint16_t*>(O2h)[o] = h;
                reinterpret_cast<uint16_t*>(O2l)[o] = l;
            }
        }
    } else if (epi == EPI_SPLIT) {   // PV -> ATT hi/lo
        size_t base = (size_t)z * sC;
#pragma unroll
        for (int i = 0; i < 64; i++) {
            int p = tid + (i << 8);
            int col = p & 127, row = p >> 7;
            float v = sm[row * LDE + col];
            uint16_t h, l;
            split1(v, h, l);
            size_t o = base + (size_t)(m0 + row) * ldc + n0 + col;
            reinterpret_cast<uint16_t*>(O0h)[o] = h;
            reinterpret_cast<uint16_t*>(O0l)[o] = l;
        }
    } else {                         // EPI_BIAS: out = acc + b0
        float* Cb = Cf + (size_t)z * sC;
#pragma unroll
        for (int i = 0; i < 64; i++) {
            int p = tid + (i << 8);
            int col = p & 127, row = p >> 7;
            Cb[(size_t)(m0 + row) * ldc + n0 + col] = sm[row * LDE + col] + b0[n0 + col];
        }
    }
}

// split fp32 -> (hi, lo) bf16, same layout
__global__ void __launch_bounds__(256) conv_split(const float* __restrict__ in,
                                                  bf16* __restrict__ oh, bf16* __restrict__ ol,
                                                  int n4)
{
    int i = blockIdx.x * blockDim.x + threadIdx.x;
    if (i >= n4) return;
    float4 v = reinterpret_cast<const float4*>(in)[i];
    uint16_t h0, l0, h1, l1, h2, l2, h3, l3;
    split1(v.x, h0, l0); split1(v.y, h1, l1); split1(v.z, h2, l2); split1(v.w, h3, l3);
    uint2 H = make_uint2((uint32_t)h0 | ((uint32_t)h1 << 16), (uint32_t)h2 | ((uint32_t)h3 << 16));
    uint2 L = make_uint2((uint32_t)l0 | ((uint32_t)l1 << 16), (uint32_t)l2 | ((uint32_t)l3 << 16));
    reinterpret_cast<uint2*>(oh)[i] = H;
    reinterpret_cast<uint2*>(ol)[i] = L;
}

// out[n][k] = in[k][n], split into bf16 hi/lo.  2048x2048.
__global__ void __launch_bounds__(256) transpose_split(const float* __restrict__ in,
                                                       bf16* __restrict__ oh, bf16* __restrict__ ol)
{
    __shared__ float t[32][33];
    int tx = threadIdx.x & 31, ty = threadIdx.x >> 5;
    int bx = blockIdx.x, by = blockIdx.y;
    int xin = bx * 32 + tx;
#pragma unroll
    for (int j = 0; j < 4; j++) {
        int yin = by * 32 + ty + j * 8;
        t[ty + j * 8][tx] = in[(size_t)yin * H_DIM + xin];
    }
    __syncthreads();
#pragma unroll
    for (int j = 0; j < 4; j++) {
        int n = bx * 32 + ty + j * 8;
        int k = by * 32 + tx;
        uint16_t h, l;
        split1(t[tx][ty + j * 8], h, l);
        reinterpret_cast<uint16_t*>(oh)[(size_t)n * H_DIM + k] = h;
        reinterpret_cast<uint16_t*>(ol)[(size_t)n * H_DIM + k] = l;
    }
}

// row softmax over 2048 keys + fused bf16 hi/lo split of probs
__global__ void __launch_bounds__(256) softmax_conv(const float* __restrict__ Sc,
                                                    bf16* __restrict__ Ph, bf16* __restrict__ Pl)
{
    size_t base = (size_t)blockIdx.x * S_DIM;
    int tid = threadIdx.x;
    __shared__ float red[32];

    float v[8];
    float m = -3.402823e38f;
#pragma unroll
    for (int i = 0; i < 8; i++) {
        v[i] = Sc[base + tid + (i << 8)];
        m = fmaxf(m, v[i]);
    }
#pragma unroll
    for (int o = 16; o > 0; o >>= 1) m = fmaxf(m, __shfl_xor_sync(0xffffffffu, m, o));
    if ((tid & 31) == 0) red[tid >> 5] = m;
    __syncthreads();
    if (tid < 32) {
        float bm = (tid < 8) ? red[tid] : -3.402823e38f;
#pragma unroll
        for (int o = 4; o > 0; o >>= 1) bm = fmaxf(bm, __shfl_xor_sync(0xffffffffu, bm, o));
        if (tid == 0) red[0] = bm;
    }
    __syncthreads();
    m = red[0];

    float s = 0.f;
#pragma unroll
    for (int i = 0; i < 8; i++) {
        v[i] = expf(v[i] - m);
        s += v[i];
    }
    __syncthreads();
#pragma unroll
    for (int o = 16; o > 0; o >>= 1) s += __shfl_xor_sync(0xffffffffu, s, o);
    if ((tid & 31) == 0) red[tid >> 5] = s;
    __syncthreads();
    if (tid < 32) {
        float bs = (tid < 8) ? red[tid] : 0.f;
#pragma unroll
        for (int o = 4; o > 0; o >>= 1) bs += __shfl_xor_sync(0xffffffffu, bs, o);
        if (tid == 0) red[0] = bs;
    }
    __syncthreads();
    float inv = 1.0f / red[0];
#pragma unroll
    for (int i = 0; i < 8; i++) {
        float p = v[i] * inv;
        uint16_t h, l;
        split1(p, h, l);
        reinterpret_cast<uint16_t*>(Ph)[base + tid + (i << 8)] = h;
        reinterpret_cast<uint16_t*>(Pl)[base + tid + (i << 8)] = l;
    }
}

// =================================================================================
// launch
// =================================================================================
extern "C" void kernel_launch(void* const* d_in, const int* in_sizes, int n_in,
                              void* d_out, int out_size)
{
    const float* X  = (const float*)d_in[0];
    const float* wq = (const float*)d_in[1];
    const float* bq = (const float*)d_in[2];
    const float* wk = (const float*)d_in[3];
    const float* bk = (const float*)d_in[4];
    const float* wv = (const float*)d_in[5];
    const float* bv = (const float*)d_in[6];
    const float* wo = (const float*)d_in[7];
    const float* bo = (const float*)d_in[8];
    float* out = (float*)d_out;

    bf16 *Xh, *Xl, *WTh, *WTl, *Qh, *Ql, *Kh, *Kl, *VTh, *VTl, *ATTh, *ATTl, *Ph, *Pl;
    float *SCR;
    cudaGetSymbolAddress((void**)&Xh, g_Xh);     cudaGetSymbolAddress((void**)&Xl, g_Xl);
    cudaGetSymbolAddress((void**)&WTh, g_WTh);   cudaGetSymbolAddress((void**)&WTl, g_WTl);
    cudaGetSymbolAddress((void**)&Qh, g_Qh);     cudaGetSymbolAddress((void**)&Ql, g_Ql);
    cudaGetSymbolAddress((void**)&Kh, g_Kh);     cudaGetSymbolAddress((void**)&Kl, g_Kl);
    cudaGetSymbolAddress((void**)&VTh, g_VTh);   cudaGetSymbolAddress((void**)&VTl, g_VTl);
    cudaGetSymbolAddress((void**)&ATTh, g_ATTh); cudaGetSymbolAddress((void**)&ATTl, g_ATTl);
    cudaGetSymbolAddress((void**)&Ph, g_Ph);     cudaGetSymbolAddress((void**)&Pl, g_Pl);
    cudaGetSymbolAddress((void**)&SCR, g_scores);

    cudaFuncSetAttribute(gemm_epi, cudaFuncAttributeMaxDynamicSharedMemorySize, SMEM_DYN);

    const int TPB = 256;
    const long long SS  = (long long)S_DIM * S_DIM;
    const long long SVB = (long long)HD * S_DIM;
    dim3 tgrid(64, 64, 1);

    // X -> bf16 hi/lo
    conv_split<<<4096, TPB>>>(X, Xh, Xl, S_DIM * H_DIM / 4);

    // transpose+split all three projection weights into concatenated buffer
    transpose_split<<<tgrid, TPB>>>(wq, WTh,                WTl);
    transpose_split<<<tgrid, TPB>>>(wk, WTh + ELEM_SQ,      WTl + ELEM_SQ);
    transpose_split<<<tgrid, TPB>>>(wv, WTh + 2 * ELEM_SQ,  WTl + 2 * ELEM_SQ);

    // QKV batched GEMM with fused bias+rope+split / bias+transpose+split epilogues
    dim3 gQKV(16, 16, 3);
    gemm_epi<<<gQKV, TPB, SMEM_DYN>>>(Xh, Xl, WTh, WTl, nullptr,
                                      Qh, Ql, Kh, Kl, VTh, VTl,
                                      bq, bk, bv,
                                      EPI_QKV, H_DIM, H_DIM, H_DIM, 0,
                                      0, (long long)ELEM_SQ, 0);

    // scores[h] = Qs_h @ K_h^T  (fp32 direct store)
    dim3 gScores(16, 16, NHEAD);
    gemm_epi<<<gScores, TPB, SMEM_DYN>>>(Qh, Ql, Kh, Kl, SCR,
                                         nullptr, nullptr, nullptr, nullptr, nullptr, nullptr,
                                         nullptr, nullptr, nullptr,
                                         EPI_F32, HD, H_DIM, H_DIM, S_DIM,
                                         HD, HD, SS);

    // softmax + split probs
    softmax_conv<<<NHEAD * S_DIM, TPB>>>(SCR, Ph, Pl);

    // attn[h] = P_h @ V_h  with fused hi/lo-split epilogue -> ATT
    dim3 gPV(1, 16, NHEAD);
    gemm_epi<<<gPV, TPB, SMEM_DYN>>>(Ph, Pl, VTh, VTl, nullptr,
                                     ATTh, ATTl, nullptr, nullptr, nullptr, nullptr,
                                     nullptr, nullptr, nullptr,
                                     EPI_SPLIT, S_DIM, S_DIM, S_DIM, H_DIM,
                                     SS, SVB, HD);

    // out = attn @ wo + bo  (fused bias epilogue)
    transpose_split<<<tgrid, TPB>>>(wo, WTh, WTl);
    dim3 gOut(16, 16, 1);
    gemm_epi<<<gOut, TPB, SMEM_DYN>>>(ATTh, ATTl, WTh, WTl, out,
                                      nullptr, nullptr, nullptr, nullptr, nullptr, nullptr,
                                      bo, nullptr, nullptr,
                                      EPI_BIAS, H_DIM, H_DIM, H_DIM, H_DIM,
                                      0, 0, 0);
}